// round 12
// baseline (speedup 1.0000x reference)
#include <cuda_runtime.h>
#include <cuda_fp16.h>
#include <cstdint>
#include <cstddef>

#define NN 50000
#define NE 800000
#define NHH 8

__device__ __align__(16) __half g_xW  [(size_t)NN * 128];
__device__ __align__(16) __half g_preA[(size_t)NN * 128];
__device__ __align__(16) __half g_preB[(size_t)NN * 128];
__device__ __align__(16) float  g_a   [(size_t)NE * 8];
__device__ __align__(16) float  g_agg [(size_t)NN * 128];
__device__ float g_maxh[NHH];
__device__ float g_sumh[NHH];

__device__ __forceinline__ float silu_f(float x) { return __fdividef(x, 1.0f + __expf(-x)); }

__device__ __forceinline__ void atomicMaxF(float* addr, float val) {
    int old = __float_as_int(*addr);
    while (__int_as_float(old) < val) {
        int assumed = old;
        old = atomicCAS((int*)addr, assumed, __float_as_int(val));
        if (old == assumed) break;
    }
}

__device__ __forceinline__ uint32_t smem_u32(const void* p) {
    uint32_t a;
    asm("{ .reg .u64 t; cvta.to.shared.u64 t, %1; cvt.u32.u64 %0, t; }" : "=r"(a) : "l"(p));
    return a;
}

__device__ __forceinline__ uint32_t packh2(float a, float b) {
    __half2 h = __floats2half2_rn(a, b);
    return *reinterpret_cast<uint32_t*>(&h);
}
__device__ __forceinline__ float2 unpackh2(uint32_t u) {
    return __half22float2(*reinterpret_cast<__half2*>(&u));
}
__device__ __forceinline__ uint32_t packh2_f2(float2 v) { return packh2(v.x, v.y); }

__device__ __forceinline__ void mmah(uint32_t* c, const uint32_t* a, uint32_t b0, uint32_t b1) {
    asm volatile("mma.sync.aligned.m16n8k16.row.col.f16.f16.f16.f16 "
                 "{%0,%1}, {%2,%3,%4,%5}, {%6,%7}, {%0,%1};"
                 : "+r"(c[0]), "+r"(c[1])
                 : "r"(a[0]), "r"(a[1]), "r"(a[2]), "r"(a[3]), "r"(b0), "r"(b1));
}

__device__ __forceinline__ void ldmat4(uint32_t& r0, uint32_t& r1, uint32_t& r2, uint32_t& r3,
                                       uint32_t saddr) {
    asm volatile("ldmatrix.sync.aligned.m8n8.x4.shared.b16 {%0,%1,%2,%3}, [%4];"
                 : "=r"(r0), "=r"(r1), "=r"(r2), "=r"(r3) : "r"(saddr));
}

template<int KS, int SW>
__device__ __forceinline__ void layerH(uint32_t (&acc)[16][2], const uint32_t (&a)[8][4],
                                       uint32_t wbase, uint32_t rowsel, uint32_t kbit) {
#pragma unroll
    for (int s = 0; s < KS; s++) {
#pragma unroll
        for (int p = 0; p < 8; p++) {
            uint32_t addr = wbase + (((p * 16 + rowsel) * SW) + s * 16 + kbit) * 2;
            uint32_t b0, b1, b2, b3;
            ldmat4(b0, b1, b2, b3, addr);
            mmah(acc[2 * p],     a[s], b0, b1);
            mmah(acc[2 * p + 1], a[s], b2, b3);
        }
    }
}

__device__ __forceinline__ void zero_acc(uint32_t (&acc)[16][2]) {
#pragma unroll
    for (int nt = 0; nt < 16; nt++) { acc[nt][0] = 0u; acc[nt][1] = 0u; }
}

__device__ __forceinline__ void bias_silu(uint32_t (&acc)[16][2], const float* __restrict__ bias, int kb0) {
#pragma unroll
    for (int nt = 0; nt < 16; nt++) {
        float2 b = *reinterpret_cast<const float2*>(bias + nt * 8 + kb0);
        float2 f0 = unpackh2(acc[nt][0]);
        float2 f1 = unpackh2(acc[nt][1]);
        acc[nt][0] = packh2(silu_f(f0.x + b.x), silu_f(f0.y + b.y));
        acc[nt][1] = packh2(silu_f(f1.x + b.x), silu_f(f1.y + b.y));
    }
}
__device__ __forceinline__ void to_afrag(const uint32_t (&acc)[16][2], uint32_t (&a)[8][4]) {
#pragma unroll
    for (int s = 0; s < 8; s++) {
        a[s][0] = acc[2*s][0];   a[s][1] = acc[2*s][1];
        a[s][2] = acc[2*s+1][0]; a[s][3] = acc[2*s+1][1];
    }
}

#define SW_K32  40
#define SW_K128 136
#define SW_K64  72
#define SW_K16  24
#define ATT_THREADS 192
#define ATT_WARPS 6
#define ATT_GRID 444
#define MSG_THREADS 256
#define MSG_WARPS 8
#define MSG_GRID 296

// ===================== node precompute via mma (xW, preA, preB) =====================
__global__ void __launch_bounds__(ATT_THREADS, 3) node_pre_mma_kernel(
    const float* __restrict__ nf, const float* __restrict__ Wnode,
    const float* __restrict__ aW1) {
    extern __shared__ char smch[];
    __half* sWn = (__half*)smch;                // [128][136]
    __half* sWa = sWn + 128 * SW_K128;          // [128][72]
    __half* sWb = sWa + 128 * SW_K64;           // [128][72]

    int t = threadIdx.x;
    for (int i = t; i < 16384; i += ATT_THREADS) {
        int k = i >> 7, n = i & 127;
        sWn[n * SW_K128 + k] = __float2half(Wnode[i]);
    }
    for (int i = t; i < 8192; i += ATT_THREADS) {
        int k = i >> 7, n = i & 127;
        sWa[n * SW_K64 + k] = __float2half(aW1[i]);
        sWb[n * SW_K64 + k] = __float2half(aW1[8192 + i]);
    }
    __syncthreads();

    uint32_t bWn = smem_u32(sWn), bWa = smem_u32(sWa), bWb = smem_u32(sWb);
    int lane = t & 31, warp = t >> 5;
    uint32_t rowsel = (uint32_t)(((lane >> 4) << 3) | (lane & 7));
    uint32_t kbit = (uint32_t)(((lane >> 3) & 1) * 8);
    int kb0 = (lane & 3) * 2;

    int gw = blockIdx.x * ATT_WARPS + warp;
    int nw = gridDim.x * ATT_WARPS;
    for (int wt = gw; wt < NN / 16; wt += nw) {
        int r0 = wt * 16 + (lane >> 2), r1 = r0 + 8;
        uint32_t a[8][4];
#pragma unroll
        for (int s = 0; s < 8; s++) {
            int kb = 16 * s + kb0;
            a[s][0] = packh2_f2(*(const float2*)(nf + (size_t)r0 * 128 + kb));
            a[s][1] = packh2_f2(*(const float2*)(nf + (size_t)r1 * 128 + kb));
            a[s][2] = packh2_f2(*(const float2*)(nf + (size_t)r0 * 128 + kb + 8));
            a[s][3] = packh2_f2(*(const float2*)(nf + (size_t)r1 * 128 + kb + 8));
        }
        uint32_t acc[16][2];
        zero_acc(acc);
        layerH<8, SW_K128>(acc, a, bWn, rowsel, kbit);
#pragma unroll
        for (int nt = 0; nt < 16; nt++) {
            int col = nt * 8 + kb0;
            *(uint32_t*)(g_xW + (size_t)r0 * 128 + col) = acc[nt][0];
            *(uint32_t*)(g_xW + (size_t)r1 * 128 + col) = acc[nt][1];
        }
        zero_acc(acc);
        layerH<4, SW_K64>(acc, a, bWa, rowsel, kbit);
#pragma unroll
        for (int nt = 0; nt < 16; nt++) {
            int col = nt * 8 + kb0;
            *(uint32_t*)(g_preA + (size_t)r0 * 128 + col) = acc[nt][0];
            *(uint32_t*)(g_preA + (size_t)r1 * 128 + col) = acc[nt][1];
        }
        zero_acc(acc);
        layerH<4, SW_K64>(acc, a, bWb, rowsel, kbit);
#pragma unroll
        for (int nt = 0; nt < 16; nt++) {
            int col = nt * 8 + kb0;
            *(uint32_t*)(g_preB + (size_t)r0 * 128 + col) = acc[nt][0];
            *(uint32_t*)(g_preB + (size_t)r1 * 128 + col) = acc[nt][1];
        }
    }
}

// ===================== edge_msg + fused scatter (v4 atomics via pair shuffle) =====================
__global__ void __launch_bounds__(MSG_THREADS, 2) edge_msg_scatter_kernel(
    const float* __restrict__ edge_attr, const float* __restrict__ edge_sh,
    const float* __restrict__ fc1, const float* __restrict__ b1,
    const float* __restrict__ fc2, const float* __restrict__ b2,
    const float* __restrict__ fc3, const float* __restrict__ b3,
    const float* __restrict__ Wsh, const int* __restrict__ ei) {
    extern __shared__ char smch[];
    __half* sFc1 = (__half*)smch;                   // [128][40]
    __half* sFc2 = sFc1 + 128 * SW_K32;             // [128][136]
    __half* sFc3 = sFc2 + 128 * SW_K128;            // [128][136]
    __half* sWsh = sFc3 + 128 * SW_K128;            // [128][24]
    float* sB1 = (float*)(sWsh + 128 * SW_K16);
    float* sB2 = sB1 + 128;
    float* sB3 = sB2 + 128;

    int t = threadIdx.x;
    for (int i = t; i < 4096; i += MSG_THREADS) {
        int k = i >> 7, n = i & 127;
        sFc1[n * SW_K32 + k] = __float2half(fc1[i]);
    }
    for (int i = t; i < 16384; i += MSG_THREADS) {
        int k = i >> 7, n = i & 127;
        sFc2[n * SW_K128 + k] = __float2half(fc2[i]);
        sFc3[n * SW_K128 + k] = __float2half(fc3[i]);
    }
    for (int i = t; i < 2048; i += MSG_THREADS) {
        int k = i >> 7, n = i & 127;
        sWsh[n * SW_K16 + k] = __float2half(Wsh[i]);
    }
    if (t < 128) { sB1[t] = b1[t]; sB2[t] = b2[t]; sB3[t] = b3[t]; }
    __syncthreads();

    uint32_t bFc1 = smem_u32(sFc1), bFc2 = smem_u32(sFc2), bFc3 = smem_u32(sFc3), bWsh = smem_u32(sWsh);
    int lane = t & 31, warp = t >> 5;
    uint32_t rowsel = (uint32_t)(((lane >> 4) << 3) | (lane & 7));
    uint32_t kbit = (uint32_t)(((lane >> 3) & 1) * 8);
    int kb0 = (lane & 3) * 2;
    bool upper = (lane & 1);

    float mh0 = g_maxh[kb0], mh1 = g_maxh[kb0 + 1];
    float inv0 = __frcp_rn(g_sumh[kb0]), inv1 = __frcp_rn(g_sumh[kb0 + 1]);

    int gw = blockIdx.x * MSG_WARPS + warp;
    int nw = gridDim.x * MSG_WARPS;
    for (int wt = gw; wt < NE / 16; wt += nw) {
        int r0 = wt * 16 + (lane >> 2), r1 = r0 + 8;
        int src0 = ei[r0], src1 = ei[r1];
        int d0 = ei[NE + r0], d1 = ei[NE + r1];

        // alpha_mean: quad covers all 8 heads (kb0 in {0,2,4,6})
        float2 aR0 = *(const float2*)(g_a + (size_t)r0 * 8 + kb0);
        float2 aR1 = *(const float2*)(g_a + (size_t)r1 * 8 + kb0);
        float am0 = __expf(aR0.x - mh0) * inv0 + __expf(aR0.y - mh1) * inv1;
        float am1 = __expf(aR1.x - mh0) * inv0 + __expf(aR1.y - mh1) * inv1;
        am0 += __shfl_xor_sync(0xffffffffu, am0, 1);
        am0 += __shfl_xor_sync(0xffffffffu, am0, 2);
        am1 += __shfl_xor_sync(0xffffffffu, am1, 1);
        am1 += __shfl_xor_sync(0xffffffffu, am1, 2);
        am0 *= 0.125f; am1 *= 0.125f;

        uint32_t a[8][4];
#pragma unroll
        for (int s = 0; s < 2; s++) {
            int kb = kb0 + 16 * s;
            a[s][0] = packh2_f2(*(const float2*)(edge_attr + (size_t)r0 * 32 + kb));
            a[s][1] = packh2_f2(*(const float2*)(edge_attr + (size_t)r1 * 32 + kb));
            a[s][2] = packh2_f2(*(const float2*)(edge_attr + (size_t)r0 * 32 + kb + 8));
            a[s][3] = packh2_f2(*(const float2*)(edge_attr + (size_t)r1 * 32 + kb + 8));
        }
        uint32_t ash[4];
        ash[0] = packh2_f2(*(const float2*)(edge_sh + (size_t)r0 * 16 + kb0));
        ash[1] = packh2_f2(*(const float2*)(edge_sh + (size_t)r1 * 16 + kb0));
        ash[2] = packh2_f2(*(const float2*)(edge_sh + (size_t)r0 * 16 + kb0 + 8));
        ash[3] = packh2_f2(*(const float2*)(edge_sh + (size_t)r1 * 16 + kb0 + 8));

        uint32_t acc[16][2];
        zero_acc(acc);
        layerH<2, SW_K32>(acc, a, bFc1, rowsel, kbit);
        bias_silu(acc, sB1, kb0); to_afrag(acc, a);
        zero_acc(acc);
        layerH<8, SW_K128>(acc, a, bFc2, rowsel, kbit);
        bias_silu(acc, sB2, kb0); to_afrag(acc, a);
        zero_acc(acc);
        layerH<8, SW_K128>(acc, a, bFc3, rowsel, kbit);   // scale (pre-bias)

        // epilogue: msg*alpha_mean -> red.v4 via pair exchange (lane^1)
        // lower lane covers r0 cols [c..c+3], upper lane covers r1 cols [c..c+3]
        float* aggRow = upper ? (g_agg + (size_t)d1 * 128) : (g_agg + (size_t)d0 * 128);
        int colbase = (kb0 & ~3) | (kb0 & 1);   // lower's kb0 (pair base): 0,0,4,4
#pragma unroll
        for (int p = 0; p < 8; p++) {
            uint32_t b0, b1, b2, b3;
            uint32_t addr = bWsh + (((p * 16 + rowsel) * SW_K16) + kbit) * 2;
            ldmat4(b0, b1, b2, b3, addr);
            uint32_t t0[2] = {0u, 0u}, t1[2] = {0u, 0u};
            mmah(t0, ash, b0, b1);
            mmah(t1, ash, b2, b3);
#pragma unroll
            for (int q = 0; q < 2; q++) {
                int nt = 2 * p + q;
                const uint32_t* tv = q ? t1 : t0;
                int col = nt * 8 + kb0;
                float2 bv = *(const float2*)(sB3 + col);
                float2 sc0 = unpackh2(acc[nt][0]), sc1 = unpackh2(acc[nt][1]);
                float2 sh0 = unpackh2(tv[0]), sh1 = unpackh2(tv[1]);
                float2 xw0 = unpackh2(*(const uint32_t*)(g_xW + (size_t)src0 * 128 + col));
                float2 xw1 = unpackh2(*(const uint32_t*)(g_xW + (size_t)src1 * 128 + col));
                float v0x = silu_f(fmaf(xw0.x, sc0.x + bv.x, sh0.x)) * am0;
                float v0y = silu_f(fmaf(xw0.y, sc0.y + bv.y, sh0.y)) * am0;
                float v1x = silu_f(fmaf(xw1.x, sc1.x + bv.x, sh1.x)) * am1;
                float v1y = silu_f(fmaf(xw1.y, sc1.y + bv.y, sh1.y)) * am1;
                // exchange: lower sends r1 pair, upper sends r0 pair
                float sx = upper ? v0x : v1x;
                float sy = upper ? v0y : v1y;
                float ex = __shfl_xor_sync(0xffffffffu, sx, 1);
                float ey = __shfl_xor_sync(0xffffffffu, sy, 1);
                float a0 = upper ? ex : v0x;
                float a1 = upper ? ey : v0y;
                float a2 = upper ? v1x : ex;
                float a3 = upper ? v1y : ey;
                asm volatile("red.global.add.v4.f32 [%0], {%1, %2, %3, %4};"
                             :: "l"(aggRow + nt * 8 + colbase),
                                "f"(a0), "f"(a1), "f"(a2), "f"(a3) : "memory");
            }
        }
    }
}

// ===================== edge_att (persistent, f16 mma, fused head-max) =====================
__global__ void __launch_bounds__(ATT_THREADS, 3) edge_att_mma_kernel(
    const float* __restrict__ edge_attr,
    const float* __restrict__ aW1, const float* __restrict__ ab1,
    const float* __restrict__ aW2, const float* __restrict__ ab2,
    const float* __restrict__ aW3, const float* __restrict__ ab3,
    const int* __restrict__ ei) {
    extern __shared__ char smch[];
    __half* sA1e = (__half*)smch;                   // [128][40]
    __half* sA2  = sA1e + 128 * SW_K32;             // [128][136]
    __half* sA3  = sA2 + 128 * SW_K128;             // [8][136]
    float* sAb1 = (float*)(sA3 + 8 * SW_K128);
    float* sAb2 = sAb1 + 128;
    float* sAb3 = sAb2 + 128;
    __shared__ float sBMax[ATT_WARPS][8];

    int t = threadIdx.x;
    for (int i = t; i < 4096; i += ATT_THREADS) {
        int k = i >> 7, n = i & 127;
        sA1e[n * SW_K32 + k] = __float2half(aW1[(128 + k) * 128 + n]);
    }
    for (int i = t; i < 16384; i += ATT_THREADS) {
        int k = i >> 7, n = i & 127;
        sA2[n * SW_K128 + k] = __float2half(aW2[i]);
    }
    for (int i = t; i < 1024; i += ATT_THREADS) {
        int k = i >> 3, n = i & 7;
        sA3[n * SW_K128 + k] = __float2half(aW3[i]);
    }
    if (t < 128) { sAb1[t] = ab1[t]; sAb2[t] = ab2[t]; }
    if (t < 8) sAb3[t] = ab3[t];
    __syncthreads();

    uint32_t bA1e = smem_u32(sA1e), bA2 = smem_u32(sA2);
    int lane = t & 31, warp = t >> 5;
    uint32_t rowsel = (uint32_t)(((lane >> 4) << 3) | (lane & 7));
    uint32_t kbit = (uint32_t)(((lane >> 3) & 1) * 8);
    int kb0 = (lane & 3) * 2;

    float mxA = -3.0e38f, mxB = -3.0e38f;

    int gw = blockIdx.x * ATT_WARPS + warp;
    int nw = gridDim.x * ATT_WARPS;
    for (int wt = gw; wt < NE / 16; wt += nw) {
        int r0 = wt * 16 + (lane >> 2), r1 = r0 + 8;
        int src0 = ei[r0], src1 = ei[r1];
        int dst0 = ei[NE + r0], dst1 = ei[NE + r1];

        uint32_t a[8][4];
#pragma unroll
        for (int s = 0; s < 2; s++) {
            int kb = kb0 + 16 * s;
            a[s][0] = packh2_f2(*(const float2*)(edge_attr + (size_t)r0 * 32 + kb));
            a[s][1] = packh2_f2(*(const float2*)(edge_attr + (size_t)r1 * 32 + kb));
            a[s][2] = packh2_f2(*(const float2*)(edge_attr + (size_t)r0 * 32 + kb + 8));
            a[s][3] = packh2_f2(*(const float2*)(edge_attr + (size_t)r1 * 32 + kb + 8));
        }
        uint32_t acc[16][2];
        zero_acc(acc);
        layerH<2, SW_K32>(acc, a, bA1e, rowsel, kbit);
#pragma unroll
        for (int nt = 0; nt < 16; nt++) {
            int col = nt * 8 + kb0;
            float2 bv = *(const float2*)(sAb1 + col);
            float2 f0 = unpackh2(acc[nt][0]);
            float2 f1 = unpackh2(acc[nt][1]);
            float2 pa0 = unpackh2(*(const uint32_t*)(g_preA + (size_t)src0 * 128 + col));
            float2 pb0 = unpackh2(*(const uint32_t*)(g_preB + (size_t)dst0 * 128 + col));
            float2 pa1 = unpackh2(*(const uint32_t*)(g_preA + (size_t)src1 * 128 + col));
            float2 pb1 = unpackh2(*(const uint32_t*)(g_preB + (size_t)dst1 * 128 + col));
            acc[nt][0] = packh2(silu_f(f0.x + bv.x + pa0.x + pb0.x),
                                silu_f(f0.y + bv.y + pa0.y + pb0.y));
            acc[nt][1] = packh2(silu_f(f1.x + bv.x + pa1.x + pb1.x),
                                silu_f(f1.y + bv.y + pa1.y + pb1.y));
        }
        uint32_t a2[8][4];
        to_afrag(acc, a2);
        zero_acc(acc);
        layerH<8, SW_K128>(acc, a2, bA2, rowsel, kbit);
        bias_silu(acc, sAb2, kb0); to_afrag(acc, a2);
        uint32_t c3[2] = {0u, 0u};
#pragma unroll
        for (int s = 0; s < 8; s++) {
            const __half* wp = sA3 + (size_t)(lane >> 2) * SW_K128 + kb0 + 16 * s;
            mmah(c3, a2[s], *(const uint32_t*)wp, *(const uint32_t*)(wp + 8));
        }
        float2 b3 = *(const float2*)(sAb3 + kb0);
        float2 o0 = unpackh2(c3[0]), o1 = unpackh2(c3[1]);
        o0.x += b3.x; o0.y += b3.y; o1.x += b3.x; o1.y += b3.y;
        mxA = fmaxf(mxA, fmaxf(o0.x, o1.x));
        mxB = fmaxf(mxB, fmaxf(o0.y, o1.y));
        *(float2*)(g_a + (size_t)r0 * 8 + kb0) = o0;
        *(float2*)(g_a + (size_t)r1 * 8 + kb0) = o1;
    }
#pragma unroll
    for (int off = 4; off < 32; off <<= 1) {
        mxA = fmaxf(mxA, __shfl_xor_sync(0xffffffffu, mxA, off));
        mxB = fmaxf(mxB, __shfl_xor_sync(0xffffffffu, mxB, off));
    }
    if (lane < 4) { sBMax[warp][2 * lane] = mxA; sBMax[warp][2 * lane + 1] = mxB; }
    __syncthreads();
    if (t < 8) {
        float m = -3.0e38f;
        for (int w = 0; w < ATT_WARPS; w++) m = fmaxf(m, sBMax[w][t]);
        atomicMaxF(&g_maxh[t], m);
    }
}

// ===================== reductions / final =====================
__global__ void init_scalars_kernel() {
    int tid = threadIdx.x;
    if (tid < NHH) { g_maxh[tid] = -3.0e38f; g_sumh[tid] = 0.0f; }
}

__global__ void __launch_bounds__(256) redsum_kernel() {
    float mh[8], s[8];
#pragma unroll
    for (int h = 0; h < 8; h++) { mh[h] = g_maxh[h]; s[h] = 0.f; }
    int stride = gridDim.x * blockDim.x;
    for (int e = blockIdx.x * blockDim.x + threadIdx.x; e < NE; e += stride) {
        const float4* ap = reinterpret_cast<const float4*>(g_a + (size_t)e * 8);
        float4 a0 = ap[0], a1 = ap[1];
        s[0]+=__expf(a0.x-mh[0]); s[1]+=__expf(a0.y-mh[1]); s[2]+=__expf(a0.z-mh[2]); s[3]+=__expf(a0.w-mh[3]);
        s[4]+=__expf(a1.x-mh[4]); s[5]+=__expf(a1.y-mh[5]); s[6]+=__expf(a1.z-mh[6]); s[7]+=__expf(a1.w-mh[7]);
    }
#pragma unroll
    for (int off = 16; off >= 1; off >>= 1)
#pragma unroll
        for (int h = 0; h < 8; h++)
            s[h] += __shfl_xor_sync(0xffffffffu, s[h], off);
    __shared__ float ssum[8][8];
    int w = threadIdx.x >> 5, l = threadIdx.x & 31;
    if (l == 0)
        for (int h = 0; h < 8; h++) ssum[w][h] = s[h];
    __syncthreads();
    if (threadIdx.x < 8) {
        float tot = 0.f;
        for (int w2 = 0; w2 < 8; w2++) tot += ssum[w2][threadIdx.x];
        atomicAdd(&g_sumh[threadIdx.x], tot);
    }
}

__global__ void __launch_bounds__(256) final_kernel(const float* __restrict__ nf,
                                                    const float* __restrict__ Wout,
                                                    float* __restrict__ out) {
    extern __shared__ float sm[];
    float* sW = sm;
    float* sRows = sm + 16384;
    int t = threadIdx.x;
    for (int i = t; i < 16384; i += 256) sW[i] = Wout[i];
    int row0 = blockIdx.x * 32;
    for (int i = t; i < 4096; i += 256) {
        int r = row0 + (i >> 7);
        sRows[i] = (r < NN) ? g_agg[(size_t)r * 128 + (i & 127)] : 0.f;
    }
    __syncthreads();
    int warp = t >> 5, lane = t & 31;
    for (int rr = warp; rr < 32; rr += 8) {
        int r = row0 + rr;
        if (r >= NN) continue;
        const float* arow = sRows + rr * 128;
        float4 acc = make_float4(0.f,0.f,0.f,0.f);
#pragma unroll 4
        for (int k = 0; k < 128; k++) {
            float a = arow[k];
            float4 w = reinterpret_cast<const float4*>(sW + k * 128)[lane];
            acc.x = fmaf(a, w.x, acc.x); acc.y = fmaf(a, w.y, acc.y);
            acc.z = fmaf(a, w.z, acc.z); acc.w = fmaf(a, w.w, acc.w);
        }
        float4 x = reinterpret_cast<const float4*>(nf + (size_t)r * 128)[lane];
        float4 o = make_float4(x.x+acc.x, x.y+acc.y, x.z+acc.z, x.w+acc.w);
        float sum = o.x + o.y + o.z + o.w;
        float sq  = o.x*o.x + o.y*o.y + o.z*o.z + o.w*o.w;
#pragma unroll
        for (int off = 16; off >= 1; off >>= 1) {
            sum += __shfl_xor_sync(0xffffffffu, sum, off);
            sq  += __shfl_xor_sync(0xffffffffu, sq, off);
        }
        float mu = sum * (1.0f / 128.0f);
        float var = sq * (1.0f / 128.0f) - mu * mu;
        float rs = rsqrtf(var + 1e-5f);
        float4 res = make_float4((o.x-mu)*rs, (o.y-mu)*rs, (o.z-mu)*rs, (o.w-mu)*rs);
        reinterpret_cast<float4*>(out + (size_t)r * 128)[lane] = res;
    }
}

extern "C" void kernel_launch(void* const* d_in, const int* in_sizes, int n_in,
                              void* d_out, int out_size) {
    const float* nf    = (const float*)d_in[0];
    const float* eattr = (const float*)d_in[1];
    const float* esh   = (const float*)d_in[2];
    const float* Wnode = (const float*)d_in[3];
    const float* fc1   = (const float*)d_in[4];
    const float* b1    = (const float*)d_in[5];
    const float* fc2   = (const float*)d_in[6];
    const float* b2    = (const float*)d_in[7];
    const float* fc3   = (const float*)d_in[8];
    const float* b3    = (const float*)d_in[9];
    const float* Wsh   = (const float*)d_in[10];
    const float* aW1   = (const float*)d_in[11];
    const float* ab1   = (const float*)d_in[12];
    const float* aW2   = (const float*)d_in[13];
    const float* ab2   = (const float*)d_in[14];
    const float* aW3   = (const float*)d_in[15];
    const float* ab3   = (const float*)d_in[16];
    const float* Wout  = (const float*)d_in[17];
    const int*   ei    = (const int*)d_in[18];
    float* out = (float*)d_out;

    const int SM_NODE  = (128*SW_K128 + 2*128*SW_K64) * 2;
    const int SM_MSG   = (128*SW_K32 + 2*128*SW_K128 + 128*SW_K16) * 2 + 3 * 128 * 4 + 64;
    const int SM_ATT   = (128*SW_K32 + 128*SW_K128 + 8*SW_K128) * 2 + (128+128+8) * 4 + 64;
    const int SM_FINAL = (16384 + 4096) * 4;
    cudaFuncSetAttribute(node_pre_mma_kernel,     cudaFuncAttributeMaxDynamicSharedMemorySize, SM_NODE);
    cudaFuncSetAttribute(edge_msg_scatter_kernel, cudaFuncAttributeMaxDynamicSharedMemorySize, SM_MSG);
    cudaFuncSetAttribute(edge_att_mma_kernel,     cudaFuncAttributeMaxDynamicSharedMemorySize, SM_ATT);
    cudaFuncSetAttribute(final_kernel,            cudaFuncAttributeMaxDynamicSharedMemorySize, SM_FINAL);

    void* aggPtr = nullptr;
    cudaGetSymbolAddress(&aggPtr, g_agg);
    cudaMemsetAsync(aggPtr, 0, (size_t)NN * 128 * sizeof(float));

    init_scalars_kernel<<<1, 32>>>();
    node_pre_mma_kernel<<<ATT_GRID, ATT_THREADS, SM_NODE>>>(nf, Wnode, aW1);
    edge_att_mma_kernel<<<ATT_GRID, ATT_THREADS, SM_ATT>>>(eattr, aW1, ab1, aW2, ab2, aW3, ab3, ei);
    redsum_kernel<<<512, 256>>>();
    edge_msg_scatter_kernel<<<MSG_GRID, MSG_THREADS, SM_MSG>>>(eattr, esh, fc1, b1, fc2, b2, fc3, b3, Wsh, ei);
    final_kernel<<<(NN + 31) / 32, 256, SM_FINAL>>>(nf, Wout, out);
}

// round 14
// speedup vs baseline: 1.2631x; 1.2631x over previous
#include <cuda_runtime.h>
#include <cuda_fp16.h>
#include <cstdint>
#include <cstddef>

#define NN 50000
#define NE 800000
#define NHH 8

__device__ __align__(16) __half g_xW  [(size_t)NN * 128];
__device__ __align__(16) __half g_preA[(size_t)NN * 128];
__device__ __align__(16) __half g_preB[(size_t)NN * 128];
__device__ __align__(16) float  g_a   [(size_t)NE * 8];
__device__ __align__(16) float  g_agg [(size_t)NN * 128];
__device__ float g_maxh[NHH];
__device__ float g_sumh[NHH];

__device__ __forceinline__ float silu_f(float x) { return __fdividef(x, 1.0f + __expf(-x)); }

__device__ __forceinline__ void atomicMaxF(float* addr, float val) {
    int old = __float_as_int(*addr);
    while (__int_as_float(old) < val) {
        int assumed = old;
        old = atomicCAS((int*)addr, assumed, __float_as_int(val));
        if (old == assumed) break;
    }
}

__device__ __forceinline__ uint32_t smem_u32(const void* p) {
    uint32_t a;
    asm("{ .reg .u64 t; cvta.to.shared.u64 t, %1; cvt.u32.u64 %0, t; }" : "=r"(a) : "l"(p));
    return a;
}

__device__ __forceinline__ uint32_t packh2(float a, float b) {
    __half2 h = __floats2half2_rn(a, b);
    return *reinterpret_cast<uint32_t*>(&h);
}
__device__ __forceinline__ float2 unpackh2(uint32_t u) {
    return __half22float2(*reinterpret_cast<__half2*>(&u));
}
__device__ __forceinline__ uint32_t packh2_f2(float2 v) { return packh2(v.x, v.y); }

__device__ __forceinline__ void mmah(uint32_t* c, const uint32_t* a, uint32_t b0, uint32_t b1) {
    asm volatile("mma.sync.aligned.m16n8k16.row.col.f16.f16.f16.f16 "
                 "{%0,%1}, {%2,%3,%4,%5}, {%6,%7}, {%0,%1};"
                 : "+r"(c[0]), "+r"(c[1])
                 : "r"(a[0]), "r"(a[1]), "r"(a[2]), "r"(a[3]), "r"(b0), "r"(b1));
}

__device__ __forceinline__ void ldmat4(uint32_t& r0, uint32_t& r1, uint32_t& r2, uint32_t& r3,
                                       uint32_t saddr) {
    asm volatile("ldmatrix.sync.aligned.m8n8.x4.shared.b16 {%0,%1,%2,%3}, [%4];"
                 : "=r"(r0), "=r"(r1), "=r"(r2), "=r"(r3) : "r"(saddr));
}

template<int KS, int SW>
__device__ __forceinline__ void layerH(uint32_t (&acc)[16][2], const uint32_t (&a)[8][4],
                                       uint32_t wbase, uint32_t rowsel, uint32_t kbit) {
#pragma unroll
    for (int s = 0; s < KS; s++) {
#pragma unroll
        for (int p = 0; p < 8; p++) {
            uint32_t addr = wbase + (((p * 16 + rowsel) * SW) + s * 16 + kbit) * 2;
            uint32_t b0, b1, b2, b3;
            ldmat4(b0, b1, b2, b3, addr);
            mmah(acc[2 * p],     a[s], b0, b1);
            mmah(acc[2 * p + 1], a[s], b2, b3);
        }
    }
}

__device__ __forceinline__ void zero_acc(uint32_t (&acc)[16][2]) {
#pragma unroll
    for (int nt = 0; nt < 16; nt++) { acc[nt][0] = 0u; acc[nt][1] = 0u; }
}

__device__ __forceinline__ void bias_silu(uint32_t (&acc)[16][2], const float* __restrict__ bias, int kb0) {
#pragma unroll
    for (int nt = 0; nt < 16; nt++) {
        float2 b = *reinterpret_cast<const float2*>(bias + nt * 8 + kb0);
        float2 f0 = unpackh2(acc[nt][0]);
        float2 f1 = unpackh2(acc[nt][1]);
        acc[nt][0] = packh2(silu_f(f0.x + b.x), silu_f(f0.y + b.y));
        acc[nt][1] = packh2(silu_f(f1.x + b.x), silu_f(f1.y + b.y));
    }
}
__device__ __forceinline__ void to_afrag(const uint32_t (&acc)[16][2], uint32_t (&a)[8][4]) {
#pragma unroll
    for (int s = 0; s < 8; s++) {
        a[s][0] = acc[2*s][0];   a[s][1] = acc[2*s][1];
        a[s][2] = acc[2*s+1][0]; a[s][3] = acc[2*s+1][1];
    }
}

#define SW_K32  40
#define SW_K128 136
#define SW_K64  72
#define SW_K16  24
#define ATT_THREADS 192
#define ATT_WARPS 6
#define ATT_GRID 444
#define MSG_THREADS 256
#define MSG_WARPS 8
#define MSG_GRID 296

// ===================== node precompute via mma (xW, preA, preB) =====================
__global__ void __launch_bounds__(ATT_THREADS, 3) node_pre_mma_kernel(
    const float* __restrict__ nf, const float* __restrict__ Wnode,
    const float* __restrict__ aW1) {
    extern __shared__ char smch[];
    __half* sWn = (__half*)smch;                // [128][136]
    __half* sWa = sWn + 128 * SW_K128;          // [128][72]
    __half* sWb = sWa + 128 * SW_K64;           // [128][72]

    int t = threadIdx.x;
    for (int i = t; i < 16384; i += ATT_THREADS) {
        int k = i >> 7, n = i & 127;
        sWn[n * SW_K128 + k] = __float2half(Wnode[i]);
    }
    for (int i = t; i < 8192; i += ATT_THREADS) {
        int k = i >> 7, n = i & 127;
        sWa[n * SW_K64 + k] = __float2half(aW1[i]);
        sWb[n * SW_K64 + k] = __float2half(aW1[8192 + i]);
    }
    __syncthreads();

    uint32_t bWn = smem_u32(sWn), bWa = smem_u32(sWa), bWb = smem_u32(sWb);
    int lane = t & 31, warp = t >> 5;
    uint32_t rowsel = (uint32_t)(((lane >> 4) << 3) | (lane & 7));
    uint32_t kbit = (uint32_t)(((lane >> 3) & 1) * 8);
    int kb0 = (lane & 3) * 2;

    int gw = blockIdx.x * ATT_WARPS + warp;
    int nw = gridDim.x * ATT_WARPS;
    for (int wt = gw; wt < NN / 16; wt += nw) {
        int r0 = wt * 16 + (lane >> 2), r1 = r0 + 8;
        uint32_t a[8][4];
#pragma unroll
        for (int s = 0; s < 8; s++) {
            int kb = 16 * s + kb0;
            a[s][0] = packh2_f2(*(const float2*)(nf + (size_t)r0 * 128 + kb));
            a[s][1] = packh2_f2(*(const float2*)(nf + (size_t)r1 * 128 + kb));
            a[s][2] = packh2_f2(*(const float2*)(nf + (size_t)r0 * 128 + kb + 8));
            a[s][3] = packh2_f2(*(const float2*)(nf + (size_t)r1 * 128 + kb + 8));
        }
        uint32_t acc[16][2];
        zero_acc(acc);
        layerH<8, SW_K128>(acc, a, bWn, rowsel, kbit);
#pragma unroll
        for (int nt = 0; nt < 16; nt++) {
            int col = nt * 8 + kb0;
            *(uint32_t*)(g_xW + (size_t)r0 * 128 + col) = acc[nt][0];
            *(uint32_t*)(g_xW + (size_t)r1 * 128 + col) = acc[nt][1];
        }
        zero_acc(acc);
        layerH<4, SW_K64>(acc, a, bWa, rowsel, kbit);
#pragma unroll
        for (int nt = 0; nt < 16; nt++) {
            int col = nt * 8 + kb0;
            *(uint32_t*)(g_preA + (size_t)r0 * 128 + col) = acc[nt][0];
            *(uint32_t*)(g_preA + (size_t)r1 * 128 + col) = acc[nt][1];
        }
        zero_acc(acc);
        layerH<4, SW_K64>(acc, a, bWb, rowsel, kbit);
#pragma unroll
        for (int nt = 0; nt < 16; nt++) {
            int col = nt * 8 + kb0;
            *(uint32_t*)(g_preB + (size_t)r0 * 128 + col) = acc[nt][0];
            *(uint32_t*)(g_preB + (size_t)r1 * 128 + col) = acc[nt][1];
        }
    }
}

// ===================== edge_msg + fused scatter (R10 epilogue, dst hoisted) =====================
__global__ void __launch_bounds__(MSG_THREADS, 2) edge_msg_scatter_kernel(
    const float* __restrict__ edge_attr, const float* __restrict__ edge_sh,
    const float* __restrict__ fc1, const float* __restrict__ b1,
    const float* __restrict__ fc2, const float* __restrict__ b2,
    const float* __restrict__ fc3, const float* __restrict__ b3,
    const float* __restrict__ Wsh, const int* __restrict__ ei) {
    extern __shared__ char smch[];
    __half* sFc1 = (__half*)smch;                   // [128][40]
    __half* sFc2 = sFc1 + 128 * SW_K32;             // [128][136]
    __half* sFc3 = sFc2 + 128 * SW_K128;            // [128][136]
    __half* sWsh = sFc3 + 128 * SW_K128;            // [128][24]
    float* sB1 = (float*)(sWsh + 128 * SW_K16);
    float* sB2 = sB1 + 128;
    float* sB3 = sB2 + 128;

    int t = threadIdx.x;
    for (int i = t; i < 4096; i += MSG_THREADS) {
        int k = i >> 7, n = i & 127;
        sFc1[n * SW_K32 + k] = __float2half(fc1[i]);
    }
    for (int i = t; i < 16384; i += MSG_THREADS) {
        int k = i >> 7, n = i & 127;
        sFc2[n * SW_K128 + k] = __float2half(fc2[i]);
        sFc3[n * SW_K128 + k] = __float2half(fc3[i]);
    }
    for (int i = t; i < 2048; i += MSG_THREADS) {
        int k = i >> 7, n = i & 127;
        sWsh[n * SW_K16 + k] = __float2half(Wsh[i]);
    }
    if (t < 128) { sB1[t] = b1[t]; sB2[t] = b2[t]; sB3[t] = b3[t]; }
    __syncthreads();

    uint32_t bFc1 = smem_u32(sFc1), bFc2 = smem_u32(sFc2), bFc3 = smem_u32(sFc3), bWsh = smem_u32(sWsh);
    int lane = t & 31, warp = t >> 5;
    uint32_t rowsel = (uint32_t)(((lane >> 4) << 3) | (lane & 7));
    uint32_t kbit = (uint32_t)(((lane >> 3) & 1) * 8);
    int kb0 = (lane & 3) * 2;

    float mh0 = g_maxh[kb0], mh1 = g_maxh[kb0 + 1];
    float inv0 = __frcp_rn(g_sumh[kb0]), inv1 = __frcp_rn(g_sumh[kb0 + 1]);

    int gw = blockIdx.x * MSG_WARPS + warp;
    int nw = gridDim.x * MSG_WARPS;
    for (int wt = gw; wt < NE / 16; wt += nw) {
        int r0 = wt * 16 + (lane >> 2), r1 = r0 + 8;
        int src0 = ei[r0], src1 = ei[r1];
        int d0 = ei[NE + r0], d1 = ei[NE + r1];
        float* agg0 = g_agg + (size_t)d0 * 128;
        float* agg1 = g_agg + (size_t)d1 * 128;

        float2 aR0 = *(const float2*)(g_a + (size_t)r0 * 8 + kb0);
        float2 aR1 = *(const float2*)(g_a + (size_t)r1 * 8 + kb0);
        float am0 = __expf(aR0.x - mh0) * inv0 + __expf(aR0.y - mh1) * inv1;
        float am1 = __expf(aR1.x - mh0) * inv0 + __expf(aR1.y - mh1) * inv1;
        am0 += __shfl_xor_sync(0xffffffffu, am0, 1);
        am0 += __shfl_xor_sync(0xffffffffu, am0, 2);
        am1 += __shfl_xor_sync(0xffffffffu, am1, 1);
        am1 += __shfl_xor_sync(0xffffffffu, am1, 2);
        am0 *= 0.125f; am1 *= 0.125f;

        uint32_t a[8][4];
#pragma unroll
        for (int s = 0; s < 2; s++) {
            int kb = kb0 + 16 * s;
            a[s][0] = packh2_f2(*(const float2*)(edge_attr + (size_t)r0 * 32 + kb));
            a[s][1] = packh2_f2(*(const float2*)(edge_attr + (size_t)r1 * 32 + kb));
            a[s][2] = packh2_f2(*(const float2*)(edge_attr + (size_t)r0 * 32 + kb + 8));
            a[s][3] = packh2_f2(*(const float2*)(edge_attr + (size_t)r1 * 32 + kb + 8));
        }
        uint32_t ash[4];
        ash[0] = packh2_f2(*(const float2*)(edge_sh + (size_t)r0 * 16 + kb0));
        ash[1] = packh2_f2(*(const float2*)(edge_sh + (size_t)r1 * 16 + kb0));
        ash[2] = packh2_f2(*(const float2*)(edge_sh + (size_t)r0 * 16 + kb0 + 8));
        ash[3] = packh2_f2(*(const float2*)(edge_sh + (size_t)r1 * 16 + kb0 + 8));

        uint32_t acc[16][2];
        zero_acc(acc);
        layerH<2, SW_K32>(acc, a, bFc1, rowsel, kbit);
        bias_silu(acc, sB1, kb0); to_afrag(acc, a);
        zero_acc(acc);
        layerH<8, SW_K128>(acc, a, bFc2, rowsel, kbit);
        bias_silu(acc, sB2, kb0); to_afrag(acc, a);
        zero_acc(acc);
        layerH<8, SW_K128>(acc, a, bFc3, rowsel, kbit);   // scale (pre-bias)
#pragma unroll
        for (int p = 0; p < 8; p++) {
            uint32_t b0, b1, b2, b3;
            uint32_t addr = bWsh + (((p * 16 + rowsel) * SW_K16) + kbit) * 2;
            ldmat4(b0, b1, b2, b3, addr);
            uint32_t t0[2] = {0u, 0u}, t1[2] = {0u, 0u};
            mmah(t0, ash, b0, b1);
            mmah(t1, ash, b2, b3);
#pragma unroll
            for (int q = 0; q < 2; q++) {
                int nt = 2 * p + q;
                const uint32_t* tv = q ? t1 : t0;
                int col = nt * 8 + kb0;
                float2 bv = *(const float2*)(sB3 + col);
                float2 sc0 = unpackh2(acc[nt][0]), sc1 = unpackh2(acc[nt][1]);
                float2 sh0 = unpackh2(tv[0]), sh1 = unpackh2(tv[1]);
                float2 xw0 = unpackh2(*(const uint32_t*)(g_xW + (size_t)src0 * 128 + col));
                float2 xw1 = unpackh2(*(const uint32_t*)(g_xW + (size_t)src1 * 128 + col));
                float v0x = silu_f(fmaf(xw0.x, sc0.x + bv.x, sh0.x)) * am0;
                float v0y = silu_f(fmaf(xw0.y, sc0.y + bv.y, sh0.y)) * am0;
                float v1x = silu_f(fmaf(xw1.x, sc1.x + bv.x, sh1.x)) * am1;
                float v1y = silu_f(fmaf(xw1.y, sc1.y + bv.y, sh1.y)) * am1;
                asm volatile("red.global.add.v2.f32 [%0], {%1, %2};"
                             :: "l"(agg0 + col), "f"(v0x), "f"(v0y) : "memory");
                asm volatile("red.global.add.v2.f32 [%0], {%1, %2};"
                             :: "l"(agg1 + col), "f"(v1x), "f"(v1y) : "memory");
            }
        }
    }
}

// ===================== edge_att (persistent, f16 mma, fused head-max) =====================
__global__ void __launch_bounds__(ATT_THREADS, 3) edge_att_mma_kernel(
    const float* __restrict__ edge_attr,
    const float* __restrict__ aW1, const float* __restrict__ ab1,
    const float* __restrict__ aW2, const float* __restrict__ ab2,
    const float* __restrict__ aW3, const float* __restrict__ ab3,
    const int* __restrict__ ei) {
    extern __shared__ char smch[];
    __half* sA1e = (__half*)smch;                   // [128][40]
    __half* sA2  = sA1e + 128 * SW_K32;             // [128][136]
    __half* sA3  = sA2 + 128 * SW_K128;             // [8][136]
    float* sAb1 = (float*)(sA3 + 8 * SW_K128);
    float* sAb2 = sAb1 + 128;
    float* sAb3 = sAb2 + 128;
    __shared__ float sBMax[ATT_WARPS][8];

    int t = threadIdx.x;
    for (int i = t; i < 4096; i += ATT_THREADS) {
        int k = i >> 7, n = i & 127;
        sA1e[n * SW_K32 + k] = __float2half(aW1[(128 + k) * 128 + n]);
    }
    for (int i = t; i < 16384; i += ATT_THREADS) {
        int k = i >> 7, n = i & 127;
        sA2[n * SW_K128 + k] = __float2half(aW2[i]);
    }
    for (int i = t; i < 1024; i += ATT_THREADS) {
        int k = i >> 3, n = i & 7;
        sA3[n * SW_K128 + k] = __float2half(aW3[i]);
    }
    if (t < 128) { sAb1[t] = ab1[t]; sAb2[t] = ab2[t]; }
    if (t < 8) sAb3[t] = ab3[t];
    __syncthreads();

    uint32_t bA1e = smem_u32(sA1e), bA2 = smem_u32(sA2);
    int lane = t & 31, warp = t >> 5;
    uint32_t rowsel = (uint32_t)(((lane >> 4) << 3) | (lane & 7));
    uint32_t kbit = (uint32_t)(((lane >> 3) & 1) * 8);
    int kb0 = (lane & 3) * 2;

    float mxA = -3.0e38f, mxB = -3.0e38f;

    int gw = blockIdx.x * ATT_WARPS + warp;
    int nw = gridDim.x * ATT_WARPS;
    for (int wt = gw; wt < NE / 16; wt += nw) {
        int r0 = wt * 16 + (lane >> 2), r1 = r0 + 8;
        int src0 = ei[r0], src1 = ei[r1];
        int dst0 = ei[NE + r0], dst1 = ei[NE + r1];

        uint32_t a[8][4];
#pragma unroll
        for (int s = 0; s < 2; s++) {
            int kb = kb0 + 16 * s;
            a[s][0] = packh2_f2(*(const float2*)(edge_attr + (size_t)r0 * 32 + kb));
            a[s][1] = packh2_f2(*(const float2*)(edge_attr + (size_t)r1 * 32 + kb));
            a[s][2] = packh2_f2(*(const float2*)(edge_attr + (size_t)r0 * 32 + kb + 8));
            a[s][3] = packh2_f2(*(const float2*)(edge_attr + (size_t)r1 * 32 + kb + 8));
        }
        uint32_t acc[16][2];
        zero_acc(acc);
        layerH<2, SW_K32>(acc, a, bA1e, rowsel, kbit);
#pragma unroll
        for (int nt = 0; nt < 16; nt++) {
            int col = nt * 8 + kb0;
            float2 bv = *(const float2*)(sAb1 + col);
            float2 f0 = unpackh2(acc[nt][0]);
            float2 f1 = unpackh2(acc[nt][1]);
            float2 pa0 = unpackh2(*(const uint32_t*)(g_preA + (size_t)src0 * 128 + col));
            float2 pb0 = unpackh2(*(const uint32_t*)(g_preB + (size_t)dst0 * 128 + col));
            float2 pa1 = unpackh2(*(const uint32_t*)(g_preA + (size_t)src1 * 128 + col));
            float2 pb1 = unpackh2(*(const uint32_t*)(g_preB + (size_t)dst1 * 128 + col));
            acc[nt][0] = packh2(silu_f(f0.x + bv.x + pa0.x + pb0.x),
                                silu_f(f0.y + bv.y + pa0.y + pb0.y));
            acc[nt][1] = packh2(silu_f(f1.x + bv.x + pa1.x + pb1.x),
                                silu_f(f1.y + bv.y + pa1.y + pb1.y));
        }
        uint32_t a2[8][4];
        to_afrag(acc, a2);
        zero_acc(acc);
        layerH<8, SW_K128>(acc, a2, bA2, rowsel, kbit);
        bias_silu(acc, sAb2, kb0); to_afrag(acc, a2);
        uint32_t c3[2] = {0u, 0u};
#pragma unroll
        for (int s = 0; s < 8; s++) {
            const __half* wp = sA3 + (size_t)(lane >> 2) * SW_K128 + kb0 + 16 * s;
            mmah(c3, a2[s], *(const uint32_t*)wp, *(const uint32_t*)(wp + 8));
        }
        float2 b3 = *(const float2*)(sAb3 + kb0);
        float2 o0 = unpackh2(c3[0]), o1 = unpackh2(c3[1]);
        o0.x += b3.x; o0.y += b3.y; o1.x += b3.x; o1.y += b3.y;
        mxA = fmaxf(mxA, fmaxf(o0.x, o1.x));
        mxB = fmaxf(mxB, fmaxf(o0.y, o1.y));
        *(float2*)(g_a + (size_t)r0 * 8 + kb0) = o0;
        *(float2*)(g_a + (size_t)r1 * 8 + kb0) = o1;
    }
#pragma unroll
    for (int off = 4; off < 32; off <<= 1) {
        mxA = fmaxf(mxA, __shfl_xor_sync(0xffffffffu, mxA, off));
        mxB = fmaxf(mxB, __shfl_xor_sync(0xffffffffu, mxB, off));
    }
    if (lane < 4) { sBMax[warp][2 * lane] = mxA; sBMax[warp][2 * lane + 1] = mxB; }
    __syncthreads();
    if (t < 8) {
        float m = -3.0e38f;
        for (int w = 0; w < ATT_WARPS; w++) m = fmaxf(m, sBMax[w][t]);
        atomicMaxF(&g_maxh[t], m);
    }
}

// ===================== reductions / final =====================
__global__ void init_scalars_kernel() {
    int tid = threadIdx.x;
    if (tid < NHH) { g_maxh[tid] = -3.0e38f; g_sumh[tid] = 0.0f; }
}

__global__ void __launch_bounds__(256) redsum_kernel() {
    float mh[8], s[8];
#pragma unroll
    for (int h = 0; h < 8; h++) { mh[h] = g_maxh[h]; s[h] = 0.f; }
    int stride = gridDim.x * blockDim.x;
    for (int e = blockIdx.x * blockDim.x + threadIdx.x; e < NE; e += stride) {
        const float4* ap = reinterpret_cast<const float4*>(g_a + (size_t)e * 8);
        float4 a0 = ap[0], a1 = ap[1];
        s[0]+=__expf(a0.x-mh[0]); s[1]+=__expf(a0.y-mh[1]); s[2]+=__expf(a0.z-mh[2]); s[3]+=__expf(a0.w-mh[3]);
        s[4]+=__expf(a1.x-mh[4]); s[5]+=__expf(a1.y-mh[5]); s[6]+=__expf(a1.z-mh[6]); s[7]+=__expf(a1.w-mh[7]);
    }
#pragma unroll
    for (int off = 16; off >= 1; off >>= 1)
#pragma unroll
        for (int h = 0; h < 8; h++)
            s[h] += __shfl_xor_sync(0xffffffffu, s[h], off);
    __shared__ float ssum[8][8];
    int w = threadIdx.x >> 5, l = threadIdx.x & 31;
    if (l == 0)
        for (int h = 0; h < 8; h++) ssum[w][h] = s[h];
    __syncthreads();
    if (threadIdx.x < 8) {
        float tot = 0.f;
        for (int w2 = 0; w2 < 8; w2++) tot += ssum[w2][threadIdx.x];
        atomicAdd(&g_sumh[threadIdx.x], tot);
    }
}

// final: out = LN(nf + agg @ Wout) via f16 mma; LN in fp32 (quad holds full row)
__global__ void __launch_bounds__(ATT_THREADS, 3) final_mma_kernel(
    const float* __restrict__ nf, const float* __restrict__ Wout,
    float* __restrict__ out) {
    extern __shared__ char smch[];
    __half* sW = (__half*)smch;                  // [128][136]
    int t = threadIdx.x;
    for (int i = t; i < 16384; i += ATT_THREADS) {
        int k = i >> 7, n = i & 127;
        sW[n * SW_K128 + k] = __float2half(Wout[i]);
    }
    __syncthreads();

    uint32_t bW = smem_u32(sW);
    int lane = t & 31, warp = t >> 5;
    uint32_t rowsel = (uint32_t)(((lane >> 4) << 3) | (lane & 7));
    uint32_t kbit = (uint32_t)(((lane >> 3) & 1) * 8);
    int kb0 = (lane & 3) * 2;

    int gw = blockIdx.x * ATT_WARPS + warp;
    int nw = gridDim.x * ATT_WARPS;
    for (int wt = gw; wt < NN / 16; wt += nw) {
        int r0 = wt * 16 + (lane >> 2), r1 = r0 + 8;
        uint32_t a[8][4];
#pragma unroll
        for (int s = 0; s < 8; s++) {
            int kb = 16 * s + kb0;
            a[s][0] = packh2_f2(*(const float2*)(g_agg + (size_t)r0 * 128 + kb));
            a[s][1] = packh2_f2(*(const float2*)(g_agg + (size_t)r1 * 128 + kb));
            a[s][2] = packh2_f2(*(const float2*)(g_agg + (size_t)r0 * 128 + kb + 8));
            a[s][3] = packh2_f2(*(const float2*)(g_agg + (size_t)r1 * 128 + kb + 8));
        }
        uint32_t acc[16][2];
        zero_acc(acc);
        layerH<8, SW_K128>(acc, a, bW, rowsel, kbit);
        // pass 1: stats
        float sum0 = 0.f, sq0 = 0.f, sum1 = 0.f, sq1 = 0.f;
#pragma unroll
        for (int nt = 0; nt < 16; nt++) {
            int col = nt * 8 + kb0;
            float2 x0 = *(const float2*)(nf + (size_t)r0 * 128 + col);
            float2 x1 = *(const float2*)(nf + (size_t)r1 * 128 + col);
            float2 f0 = unpackh2(acc[nt][0]);
            float2 f1 = unpackh2(acc[nt][1]);
            float o0x = f0.x + x0.x, o0y = f0.y + x0.y;
            float o1x = f1.x + x1.x, o1y = f1.y + x1.y;
            sum0 += o0x + o0y; sq0 += o0x * o0x + o0y * o0y;
            sum1 += o1x + o1y; sq1 += o1x * o1x + o1y * o1y;
        }
#pragma unroll
        for (int off = 1; off < 4; off <<= 1) {
            sum0 += __shfl_xor_sync(0xffffffffu, sum0, off);
            sq0  += __shfl_xor_sync(0xffffffffu, sq0, off);
            sum1 += __shfl_xor_sync(0xffffffffu, sum1, off);
            sq1  += __shfl_xor_sync(0xffffffffu, sq1, off);
        }
        float mu0 = sum0 * (1.0f / 128.0f);
        float var0 = sq0 * (1.0f / 128.0f) - mu0 * mu0;
        float rs0 = rsqrtf(var0 + 1e-5f);
        float mu1 = sum1 * (1.0f / 128.0f);
        float var1 = sq1 * (1.0f / 128.0f) - mu1 * mu1;
        float rs1 = rsqrtf(var1 + 1e-5f);
        // pass 2: normalize + store
#pragma unroll
        for (int nt = 0; nt < 16; nt++) {
            int col = nt * 8 + kb0;
            float2 x0 = *(const float2*)(nf + (size_t)r0 * 128 + col);
            float2 x1 = *(const float2*)(nf + (size_t)r1 * 128 + col);
            float2 f0 = unpackh2(acc[nt][0]);
            float2 f1 = unpackh2(acc[nt][1]);
            *(float2*)(out + (size_t)r0 * 128 + col) =
                make_float2((f0.x + x0.x - mu0) * rs0, (f0.y + x0.y - mu0) * rs0);
            *(float2*)(out + (size_t)r1 * 128 + col) =
                make_float2((f1.x + x1.x - mu1) * rs1, (f1.y + x1.y - mu1) * rs1);
        }
    }
}

extern "C" void kernel_launch(void* const* d_in, const int* in_sizes, int n_in,
                              void* d_out, int out_size) {
    const float* nf    = (const float*)d_in[0];
    const float* eattr = (const float*)d_in[1];
    const float* esh   = (const float*)d_in[2];
    const float* Wnode = (const float*)d_in[3];
    const float* fc1   = (const float*)d_in[4];
    const float* b1    = (const float*)d_in[5];
    const float* fc2   = (const float*)d_in[6];
    const float* b2    = (const float*)d_in[7];
    const float* fc3   = (const float*)d_in[8];
    const float* b3    = (const float*)d_in[9];
    const float* Wsh   = (const float*)d_in[10];
    const float* aW1   = (const float*)d_in[11];
    const float* ab1   = (const float*)d_in[12];
    const float* aW2   = (const float*)d_in[13];
    const float* ab2   = (const float*)d_in[14];
    const float* aW3   = (const float*)d_in[15];
    const float* ab3   = (const float*)d_in[16];
    const float* Wout  = (const float*)d_in[17];
    const int*   ei    = (const int*)d_in[18];
    float* out = (float*)d_out;

    const int SM_NODE  = (128*SW_K128 + 2*128*SW_K64) * 2;
    const int SM_MSG   = (128*SW_K32 + 2*128*SW_K128 + 128*SW_K16) * 2 + 3 * 128 * 4 + 64;
    const int SM_ATT   = (128*SW_K32 + 128*SW_K128 + 8*SW_K128) * 2 + (128+128+8) * 4 + 64;
    const int SM_FINAL = 128 * SW_K128 * 2;
    cudaFuncSetAttribute(node_pre_mma_kernel,     cudaFuncAttributeMaxDynamicSharedMemorySize, SM_NODE);
    cudaFuncSetAttribute(edge_msg_scatter_kernel, cudaFuncAttributeMaxDynamicSharedMemorySize, SM_MSG);
    cudaFuncSetAttribute(edge_att_mma_kernel,     cudaFuncAttributeMaxDynamicSharedMemorySize, SM_ATT);
    cudaFuncSetAttribute(final_mma_kernel,        cudaFuncAttributeMaxDynamicSharedMemorySize, SM_FINAL);

    void* aggPtr = nullptr;
    cudaGetSymbolAddress(&aggPtr, g_agg);
    cudaMemsetAsync(aggPtr, 0, (size_t)NN * 128 * sizeof(float));

    init_scalars_kernel<<<1, 32>>>();
    node_pre_mma_kernel<<<ATT_GRID, ATT_THREADS, SM_NODE>>>(nf, Wnode, aW1);
    edge_att_mma_kernel<<<ATT_GRID, ATT_THREADS, SM_ATT>>>(eattr, aW1, ab1, aW2, ab2, aW3, ab3, ei);
    redsum_kernel<<<512, 256>>>();
    edge_msg_scatter_kernel<<<MSG_GRID, MSG_THREADS, SM_MSG>>>(eattr, esh, fc1, b1, fc2, b2, fc3, b3, Wsh, ei);
    final_mma_kernel<<<ATT_GRID, ATT_THREADS, SM_FINAL>>>(nf, Wout, out);
}